// round 17
// baseline (speedup 1.0000x reference)
#include <cuda_runtime.h>
#include <cuda_fp16.h>
#include <math.h>
#include <stdint.h>

#define NB   64
#define NT   256
#define EMBD 512
#define VOCAB 32000
#define RNN  1024
#define Z4   4096
#define HIDN 128
#define NLAB 4

// Column permutation: original n = gate*1024 + j  ->  col' = j*4 + gate.
// fp16 scheme: h, e single fp16; U, W split hi+lo fp16.
// Cell math: fp32 only (fp16 gate math compounds through c: 9e-3 fail).
// A-pipeline: 2 buffers REQUIRE prefetch depth 1 (R15/R16 used depth 2 -> race).

// ---------------- static device scratch ----------------------------------
__device__ float g_XW[(size_t)NT * NB * Z4];
__device__ __half g_UThi[(size_t)Z4 * RNN];
__device__ __half g_UTlo[(size_t)Z4 * RNN];
__device__ __half g_WThi[(size_t)Z4 * EMBD];
__device__ __half g_WTlo[(size_t)Z4 * EMBD];
__device__ __half g_Ef16[(size_t)VOCAB * EMBD];
__device__ __half g_H2[2][64 * RNN];
__device__ float g_pooled[NB * RNN];
__device__ int   g_active[NT];
__device__ unsigned g_arrive;
__device__ int   g_release;

// ---------------- helpers --------------------------------------------------
__device__ __forceinline__ uint32_t smem_u32(const void* p) {
    return (uint32_t)__cvta_generic_to_shared(p);
}
__device__ __forceinline__ void cp_async16(uint32_t smem_dst, const void* gsrc) {
    asm volatile("cp.async.cg.shared.global [%0], [%1], 16;" :: "r"(smem_dst), "l"(gsrc));
}
__device__ __forceinline__ void cp_async4(uint32_t smem_dst, const void* gsrc) {
    asm volatile("cp.async.ca.shared.global [%0], [%1], 4;" :: "r"(smem_dst), "l"(gsrc));
}
#define CP_COMMIT() asm volatile("cp.async.commit_group;" ::: "memory")

__device__ __forceinline__ void ldsm_x4(uint32_t& r0, uint32_t& r1,
                                        uint32_t& r2, uint32_t& r3, uint32_t addr) {
    asm volatile("ldmatrix.sync.aligned.m8n8.x4.shared.b16 {%0,%1,%2,%3}, [%4];"
                 : "=r"(r0), "=r"(r1), "=r"(r2), "=r"(r3) : "r"(addr));
}
__device__ __forceinline__ void mma_f16(float* c, uint32_t a0, uint32_t a1,
                                        uint32_t a2, uint32_t a3,
                                        uint32_t b0, uint32_t b1) {
    asm volatile("mma.sync.aligned.m16n8k16.row.col.f32.f16.f16.f32 "
                 "{%0,%1,%2,%3}, {%4,%5,%6,%7}, {%8,%9}, {%0,%1,%2,%3};"
                 : "+f"(c[0]), "+f"(c[1]), "+f"(c[2]), "+f"(c[3])
                 : "r"(a0), "r"(a1), "r"(a2), "r"(a3), "r"(b0), "r"(b1));
}
__device__ __forceinline__ float fsigmoid(float x) {
    return __fdividef(1.f, 1.f + __expf(-x));
}
__device__ __forceinline__ float ftanh(float x) {
    float y;
    asm("tanh.approx.f32 %0, %1;" : "=f"(y) : "f"(x));
    return y;
}

// ---------------- prep -----------------------------------------------------
__global__ void prep_kernel(const int* __restrict__ x) {
    int t = threadIdx.x;
    if (t < NT) {
        int act = 0;
        for (int b = 0; b < NB; b++) act |= (x[b * NT + t] != 0);
        g_active[t] = act;
    }
    if (t == 0) { g_arrive = 0; g_release = 0; }
}

__global__ void zero_kernel() {
    int i = blockIdx.x * blockDim.x + threadIdx.x;
    ((uint32_t*)g_H2)[i] = 0u;
}

// ---------------- emb -> fp16 ------------------------------------------------
__global__ __launch_bounds__(256) void esplit_kernel(const float* __restrict__ emb) {
    size_t i = (size_t)blockIdx.x * 256 + threadIdx.x;
    g_Ef16[i] = __float2half_rn(emb[i]);
}

// ---------------- transpose+split+permute: U and W -------------------------
__device__ __forceinline__ int permute_col(int n) {
    return (n & 1023) * 4 + (n >> 10);
}

__global__ __launch_bounds__(256) void upack_kernel(const float* __restrict__ U) {
    __shared__ float tile[64][65];
    const int k0 = blockIdx.x * 64;
    const int n0 = blockIdx.y * 64;
    const int tid = threadIdx.x;
    #pragma unroll
    for (int it = 0; it < 16; it++) {
        int r = it * 4 + (tid >> 6);
        int c = tid & 63;
        tile[r][c] = U[(size_t)(k0 + r) * Z4 + n0 + c];
    }
    __syncthreads();
    #pragma unroll
    for (int it = 0; it < 16; it++) {
        int n = it * 4 + (tid >> 6);
        int k = tid & 63;
        float v = tile[k][n];
        __half hi = __float2half_rn(v);
        const int np = permute_col(n0 + n);
        g_UThi[(size_t)np * RNN + k0 + k] = hi;
        g_UTlo[(size_t)np * RNN + k0 + k] = __float2half_rn(v - __half2float(hi));
    }
}

__global__ __launch_bounds__(256) void wpack_kernel(const float* __restrict__ W) {
    __shared__ float tile[64][65];
    const int k0 = blockIdx.x * 64;
    const int n0 = blockIdx.y * 64;
    const int tid = threadIdx.x;
    #pragma unroll
    for (int it = 0; it < 16; it++) {
        int r = it * 4 + (tid >> 6);
        int c = tid & 63;
        tile[r][c] = W[(size_t)(k0 + r) * Z4 + n0 + c];
    }
    __syncthreads();
    #pragma unroll
    for (int it = 0; it < 16; it++) {
        int n = it * 4 + (tid >> 6);
        int k = tid & 63;
        float v = tile[k][n];
        __half hi = __float2half_rn(v);
        const int np = permute_col(n0 + n);
        g_WThi[(size_t)np * EMBD + k0 + k] = hi;
        g_WTlo[(size_t)np * EMBD + k0 + k] = __float2half_rn(v - __half2float(hi));
    }
}

// ---------------- fp16 input projection: 2 timesteps per block -------------
#define XW_A_BYTES 131072
#define XW_B_CH    16384
#define XW_SMEM    (1024 + XW_A_BYTES + 3 * XW_B_CH)

__global__ __launch_bounds__(256) void xw_mma_kernel(const int* __restrict__ x) {
    const int t0 = blockIdx.y * 2;
    const int t1 = t0 + 1;
    const int a0t = g_active[t0];
    const int a1t = g_active[t1];
    if (!a0t && !a1t) return;

    extern __shared__ char dyn[];
    __shared__ int idxs[128];
    const uint32_t tb  = (smem_u32(dyn) + 1023u) & ~1023u;
    const uint32_t ab0 = tb;
    const uint32_t bb0 = tb + XW_A_BYTES;

    const int tid  = threadIdx.x;
    const int w    = tid >> 5;
    const int lane = tid & 31;
    const int n0   = blockIdx.x * 128;
    const int mw   = w >> 1;
    const int nw   = w & 1;

    if (tid < 64)        idxs[tid] = x[tid * NT + t0];
    else if (tid < 128)  idxs[tid] = x[(tid - 64) * NT + t1];
    __syncthreads();

    #pragma unroll
    for (int it = 0; it < 32; it++) {
        const int o   = tid + 256 * it;
        const int ach = o >> 10;
        const int row = (o >> 3) & 127;
        const int cb  = o & 7;
        uint32_t off = (uint32_t)(row * 128 + cb * 16);
        uint32_t sw  = off ^ ((off >> 3) & 0x70);
        cp_async16(ab0 + ach * 16384 + sw,
                   g_Ef16 + (size_t)idxs[row] * EMBD + ach * 64 + cb * 8);
    }
    CP_COMMIT();

    auto load_b = [&](int ch, int slot) {
        const uint32_t bb = bb0 + slot * XW_B_CH;
        const __half* Bsrc = ((ch < 8) ? g_WThi : g_WTlo)
                             + (size_t)n0 * EMBD + (ch & 7) * 64;
        #pragma unroll
        for (int r = 0; r < 4; r++) {
            const int o   = tid + 256 * r;
            const int row = o >> 3;
            const int cb  = o & 7;
            uint32_t off = (uint32_t)(row * 128 + cb * 16);
            uint32_t sw  = off ^ ((off >> 3) & 0x70);
            cp_async16(bb + sw, Bsrc + (size_t)row * EMBD + cb * 8);
        }
        CP_COMMIT();
    };

    load_b(0, 0);
    load_b(1, 1);

    float c[2][4][2][4];
    #pragma unroll
    for (int i = 0; i < 2; i++)
        #pragma unroll
        for (int j = 0; j < 4; j++)
            #pragma unroll
            for (int h = 0; h < 2; h++)
                #pragma unroll
                for (int r = 0; r < 4; r++) c[i][j][h][r] = 0.f;

    const int lrow = ((lane >> 3) & 1) * 8 + (lane & 7);
    const int lcolb = (lane >> 4) * 16;

    for (int ch = 0; ch < 16; ch++) {
        if (ch + 1 < 16) asm volatile("cp.async.wait_group 1;" ::: "memory");
        else             asm volatile("cp.async.wait_group 0;" ::: "memory");
        __syncthreads();
        if (ch + 2 < 16) load_b(ch + 2, (ch + 2) % 3);

        const uint32_t ab = ab0 + (ch & 7) * 16384;
        const uint32_t bb = bb0 + (ch % 3) * XW_B_CH;

        #pragma unroll
        for (int kk = 0; kk < 4; kk++) {
            uint32_t bf[4][4];
            #pragma unroll
            for (int nt = 0; nt < 4; nt++) {
                uint32_t boff = (uint32_t)((nw * 64 + nt * 16 + lrow) * 128 + kk * 32 + lcolb);
                uint32_t baddr = bb + (boff ^ ((boff >> 3) & 0x70));
                ldsm_x4(bf[nt][0], bf[nt][1], bf[nt][2], bf[nt][3], baddr);
            }
            #pragma unroll
            for (int mt = 0; mt < 2; mt++) {
                const int mbase = mt * 64 + mw * 16;
                uint32_t aoff = (uint32_t)((mbase + lrow) * 128 + kk * 32 + lcolb);
                uint32_t aaddr = ab + (aoff ^ ((aoff >> 3) & 0x70));
                uint32_t a0, a1, a2, a3;
                ldsm_x4(a0, a1, a2, a3, aaddr);
                #pragma unroll
                for (int nt = 0; nt < 4; nt++) {
                    mma_f16(c[mt][nt][0], a0, a1, a2, a3, bf[nt][0], bf[nt][2]);
                    mma_f16(c[mt][nt][1], a0, a1, a2, a3, bf[nt][1], bf[nt][3]);
                }
            }
        }
        __syncthreads();
    }

    #pragma unroll
    for (int mt = 0; mt < 2; mt++) {
        if (!(mt ? a1t : a0t)) continue;
        float* C = g_XW + (size_t)(mt ? t1 : t0) * NB * Z4;
        #pragma unroll
        for (int nt = 0; nt < 4; nt++) {
            #pragma unroll
            for (int h = 0; h < 2; h++) {
                const int row = mw * 16 + (lane >> 2);
                const int col = n0 + nw * 64 + nt * 16 + h * 8 + (lane & 3) * 2;
                *reinterpret_cast<float2*>(C + (size_t)row * Z4 + col) =
                    make_float2(c[mt][nt][h][0], c[mt][nt][h][1]);
                *reinterpret_cast<float2*>(C + (size_t)(row + 8) * Z4 + col) =
                    make_float2(c[mt][nt][h][2], c[mt][nt][h][3]);
            }
        }
    }
}

// ---------------- persistent recurrence ------------------------------------
// K=256 chunks (4/step), 2 A-buffers with PREFETCH DEPTH 1 (race-free):
//   wait chunk ch -> syncthreads -> issue ch+1 into other slot -> compute ch.
#define A_BUFS   2
#define A_CHUNK  32768
#define B_BYTES  131072
#define XW_OFF   (B_BYTES + A_BUFS * A_CHUNK)       // 196608
#define ZB_OFF   (XW_OFF + 8192)
#define CS_OFF   (ZB_OFF + 64 * 33 * 4)
#define SX_OFF   (CS_OFF + 4096)
#define RNN_SMEM (1024 + SX_OFF + 512)

__global__ __launch_bounds__(256, 1) void rnn_persist(const int* __restrict__ x,
                                                      const float* __restrict__ bias) {
    extern __shared__ char dyn[];
    __shared__ int sact[NT];
    __shared__ float sbias[32];
    const uint32_t dynb = smem_u32(dyn);
    const uint32_t tb   = (dynb + 1023u) & ~1023u;
    const uint32_t ab0  = tb + B_BYTES;
    const uint32_t xwsm = tb + XW_OFF;
    const uint32_t sxsm = tb + SX_OFF;
    char* dynal = dyn + (tb - dynb);
    float* xws      = (float*)(dynal + XW_OFF);
    float* zbuf     = (float*)(dynal + ZB_OFF);
    float* cs       = (float*)(dynal + CS_OFF);
    float* pooled_s = cs + 512;
    int*   sx       = (int*)(dynal + SX_OFF);

    const int tid  = threadIdx.x;
    const int w    = tid >> 5;
    const int lane = tid & 31;
    const int bid  = blockIdx.x;
    const int n0   = bid * 32;
    const int j0   = bid * 8;
    const int mw   = w >> 1;
    const int nw   = w & 1;

    sact[tid] = g_active[tid];
    if (tid < 32) sbias[tid] = bias[(tid & 3) * RNN + j0 + (tid >> 2)];
    if (tid < 256) { cs[tid] = 0.f; cs[tid + 256] = 0.f;
                     pooled_s[tid] = 0.f; pooled_s[tid + 256] = 0.f; }

    // resident B: k64-chunks 0..15 = Uhi, 16..31 = Ulo
    #pragma unroll
    for (int r = 0; r < 32; r++) {
        const int o  = tid + 256 * r;
        const int ch = o >> 8;
        const int n  = (o >> 3) & 31;
        const int cb = o & 7;
        uint32_t off = (uint32_t)(n * 128 + cb * 16);
        uint32_t sw  = off ^ ((off >> 3) & 0x70);
        const __half* src =
            (ch < 16 ? g_UThi + (size_t)(n0 + n) * RNN + ch * 64
                     : g_UTlo + (size_t)(n0 + n) * RNN + (ch - 16) * 64) + cb * 8;
        cp_async16(tb + ch * 4096 + sw, src);
    }
    CP_COMMIT();
    asm volatile("cp.async.wait_group 0;" ::: "memory");
    __syncthreads();

    const int lrow = ((lane >> 3) & 1) * 8 + (lane & 7);
    const int lcolb = (lane >> 4) * 16;
    const int jl = tid & 7;
    const int b0c = tid >> 3;        // 0..31
    const int b1c = b0c + 32;        // 32..63

    int epoch = 0;
    int rb = 0;

    for (int t = 0; t < NT; t++) {
        if (!sact[t]) continue;
        const __half* Asrc = g_H2[rb];

        float c[2][2][4];
        #pragma unroll
        for (int i = 0; i < 2; i++)
            #pragma unroll
            for (int h = 0; h < 2; h++)
                #pragma unroll
                for (int r = 0; r < 4; r++) c[i][h][r] = 0.f;

        // A chunk = K=256: four 8KB subtiles
        auto load_a_ops = [&](int ch, int slot) {
            const uint32_t ab = ab0 + slot * A_CHUNK;
            #pragma unroll
            for (int r = 0; r < 8; r++) {
                const int o   = tid + 256 * r;   // 0..2047
                const int sub = o >> 9;          // 0..3
                const int row = (o >> 3) & 63;
                const int cb  = o & 7;
                uint32_t off = (uint32_t)(row * 128 + cb * 16);
                uint32_t sw  = off ^ ((off >> 3) & 0x70);
                cp_async16(ab + sub * 8192 + sw,
                           Asrc + (size_t)row * RNN + ch * 256 + sub * 64 + cb * 8);
            }
        };

        // G0: A chunk 0 + XW tile + x column
        load_a_ops(0, 0);
        #pragma unroll
        for (int r = 0; r < 2; r++) {
            const int cell = r * 256 + tid;
            const int b  = cell >> 3;
            const int jj = cell & 7;
            cp_async16(xwsm + cell * 16,
                       g_XW + ((size_t)t * NB + b) * Z4 + (size_t)(n0 + jj * 4));
        }
        if (tid < 64) cp_async4(sxsm + tid * 4, x + tid * NT + t);
        CP_COMMIT();

        for (int ch = 0; ch < 4; ch++) {
            asm volatile("cp.async.wait_group 0;" ::: "memory");
            __syncthreads();
            // prefetch depth 1: issue ch+1 into the OTHER slot (race-free)
            if (ch + 1 < 4) { load_a_ops(ch + 1, (ch + 1) & 1); CP_COMMIT(); }

            const uint32_t ab = ab0 + (ch & 1) * A_CHUNK;

            #pragma unroll
            for (int kk = 0; kk < 16; kk++) {
                const int sub = kk >> 2;
                const int k4  = kk & 3;
                uint32_t aoff = (uint32_t)((mw * 16 + lrow) * 128 + k4 * 32 + lcolb);
                uint32_t aaddr = ab + sub * 8192 + (aoff ^ ((aoff >> 3) & 0x70));
                uint32_t a0, a1, a2, a3;
                ldsm_x4(a0, a1, a2, a3, aaddr);

                const int bch = ch * 4 + sub;   // 0..15
                uint32_t boff = (uint32_t)((nw * 16 + lrow) * 128 + k4 * 32 + lcolb);
                uint32_t bsw  = boff ^ ((boff >> 3) & 0x70);
                uint32_t b0, b1, b2, b3, d0, d1, d2, d3;
                ldsm_x4(b0, b1, b2, b3, tb + bch * 4096 + bsw);
                ldsm_x4(d0, d1, d2, d3, tb + (16 + bch) * 4096 + bsw);

                mma_f16(c[0][0], a0, a1, a2, a3, b0, b2);
                mma_f16(c[0][1], a0, a1, a2, a3, b1, b3);
                mma_f16(c[1][0], a0, a1, a2, a3, d0, d2);
                mma_f16(c[1][1], a0, a1, a2, a3, d1, d3);
            }
        }
        __syncthreads();

        // epilogue -> smem z
        #pragma unroll
        for (int h = 0; h < 2; h++) {
            const int row = mw * 16 + (lane >> 2);
            const int col = nw * 16 + h * 8 + (lane & 3) * 2;
            zbuf[row * 33 + col]           = c[0][h][0] + c[1][h][0];
            zbuf[row * 33 + col + 1]       = c[0][h][1] + c[1][h][1];
            zbuf[(row + 8) * 33 + col]     = c[0][h][2] + c[1][h][2];
            zbuf[(row + 8) * 33 + col + 1] = c[0][h][3] + c[1][h][3];
        }
        __syncthreads();

        // ---- cell update: 2 cells/thread, fp32 math (validated 2.7e-6) ----
        __half* hw = g_H2[rb ^ 1];
        const __half* hr = g_H2[rb];
        {
            const float bi  = sbias[jl * 4 + 0];
            const float bfg = sbias[jl * 4 + 1];
            const float bg  = sbias[jl * 4 + 2];
            const float bo  = sbias[jl * 4 + 3];
            float4 xw0 = *reinterpret_cast<const float4*>(xws + tid * 4);
            float4 xw1 = *reinterpret_cast<const float4*>(xws + (tid + 256) * 4);

            const float zi0 = xw0.x + zbuf[b0c * 33 + jl * 4 + 0] + bi;
            const float zf0 = xw0.y + zbuf[b0c * 33 + jl * 4 + 1] + bfg;
            const float zg0 = xw0.z + zbuf[b0c * 33 + jl * 4 + 2] + bg;
            const float zo0 = xw0.w + zbuf[b0c * 33 + jl * 4 + 3] + bo;
            const float zi1 = xw1.x + zbuf[b1c * 33 + jl * 4 + 0] + bi;
            const float zf1 = xw1.y + zbuf[b1c * 33 + jl * 4 + 1] + bfg;
            const float zg1 = xw1.z + zbuf[b1c * 33 + jl * 4 + 2] + bg;
            const float zo1 = xw1.w + zbuf[b1c * 33 + jl * 4 + 3] + bo;

            const float cn0 = fsigmoid(zf0) * cs[tid] + fsigmoid(zi0) * ftanh(zg0);
            const float hn0 = fsigmoid(zo0) * ftanh(cn0);
            const float cn1 = fsigmoid(zf1) * cs[tid + 256] + fsigmoid(zi1) * ftanh(zg1);
            const float hn1 = fsigmoid(zo1) * ftanh(cn1);

            const int xv0 = sx[b0c];
            const int xv1 = sx[b1c];
            const int j = j0 + jl;
            if (xv0 != 0) { cs[tid] = cn0; hw[b0c * RNN + j] = __float2half_rn(hn0); }
            else          { hw[b0c * RNN + j] = hr[b0c * RNN + j]; }
            if (xv1 != 0) { cs[tid + 256] = cn1; hw[b1c * RNN + j] = __float2half_rn(hn1); }
            else          { hw[b1c * RNN + j] = hr[b1c * RNN + j]; }
            if (xv0 == 2) pooled_s[tid] += hn0;
            if (xv1 == 2) pooled_s[tid + 256] += hn1;
        }

        // ---- fence-free grid barrier ----
        epoch++;
        __syncthreads();
        if (tid == 0) {
            unsigned old;
            asm volatile("atom.acq_rel.gpu.global.add.u32 %0, [%1], %2;"
                         : "=r"(old) : "l"(&g_arrive), "r"(1u) : "memory");
            if (old == 127u) {
                g_arrive = 0;
                asm volatile("st.release.gpu.global.s32 [%0], %1;"
                             :: "l"(&g_release), "r"(epoch) : "memory");
            } else {
                int v;
                do {
                    asm volatile("ld.acquire.gpu.global.s32 %0, [%1];"
                                 : "=r"(v) : "l"(&g_release) : "memory");
                } while (v < epoch);
            }
        }
        __syncthreads();

        rb ^= 1;
    }

    // write pooled out
    #pragma unroll
    for (int r = 0; r < 2; r++) {
        const int cell = r * 256 + tid;
        const int b  = cell >> 3;
        const int jj = cell & 7;
        g_pooled[b * RNN + j0 + jj] = pooled_s[cell];
    }
}

// ---------------- head (precise math; errors here don't damp) --------------
__global__ __launch_bounds__(128) void head_kernel(const float* __restrict__ W1,
                                                   const float* __restrict__ b1,
                                                   const float* __restrict__ W2,
                                                   const float* __restrict__ b2,
                                                   const float* __restrict__ Wc,
                                                   const float* __restrict__ bc,
                                                   float* __restrict__ out) {
    const int b = blockIdx.x;
    const int tid = threadIdx.x;
    __shared__ float sp[RNN];
    __shared__ float h1s[HIDN];
    __shared__ float h2s[HIDN];
    __shared__ float lg[NLAB];

    for (int k = tid; k < RNN; k += 128) sp[k] = g_pooled[(size_t)b * RNN + k];
    __syncthreads();

    float a = b1[tid];
    for (int k = 0; k < RNN; k++) a += sp[k] * W1[(size_t)k * HIDN + tid];
    h1s[tid] = fmaxf(a, 0.f);
    __syncthreads();

    float a2 = b2[tid];
    for (int k = 0; k < HIDN; k++) a2 += h1s[k] * W2[(size_t)k * HIDN + tid];
    h2s[tid] = fmaxf(a2, 0.f);
    __syncthreads();

    if (tid < NLAB) {
        float l = bc[tid];
        for (int k = 0; k < HIDN; k++) l += h2s[k] * Wc[(size_t)k * NLAB + tid];
        lg[tid] = l;
    }
    __syncthreads();
    if (tid == 0) {
        const float mx = fmaxf(fmaxf(lg[0], lg[1]), fmaxf(lg[2], lg[3]));
        const float e0 = expf(lg[0] - mx), e1 = expf(lg[1] - mx);
        const float e2 = expf(lg[2] - mx), e3 = expf(lg[3] - mx);
        const float sden = e0 + e1 + e2 + e3;
        out[b * 4 + 0] = e0 / sden; out[b * 4 + 1] = e1 / sden;
        out[b * 4 + 2] = e2 / sden; out[b * 4 + 3] = e3 / sden;
    }
}

// ---------------- launcher -------------------------------------------------
extern "C" void kernel_launch(void* const* d_in, const int* in_sizes, int n_in,
                              void* d_out, int out_size) {
    const int*   x    = (const int*)d_in[0];
    const float* emb  = (const float*)d_in[1];
    const float* W    = (const float*)d_in[2];
    const float* U    = (const float*)d_in[3];
    const float* bias = (const float*)d_in[4];
    const float* W1   = (const float*)d_in[5];
    const float* b1   = (const float*)d_in[6];
    const float* W2   = (const float*)d_in[7];
    const float* b2   = (const float*)d_in[8];
    const float* Wc   = (const float*)d_in[9];
    const float* bc   = (const float*)d_in[10];
    float* out = (float*)d_out;

    cudaFuncSetAttribute(xw_mma_kernel, cudaFuncAttributeMaxDynamicSharedMemorySize, XW_SMEM);
    cudaFuncSetAttribute(rnn_persist, cudaFuncAttributeMaxDynamicSharedMemorySize, RNN_SMEM);

    prep_kernel<<<1, 256>>>(x);
    zero_kernel<<<256, 256>>>();
    esplit_kernel<<<(VOCAB * EMBD) / 256, 256>>>(emb);
    upack_kernel<<<dim3(RNN / 64, Z4 / 64), 256>>>(U);
    wpack_kernel<<<dim3(EMBD / 64, Z4 / 64), 256>>>(W);
    xw_mma_kernel<<<dim3(32, NT / 2), 256, XW_SMEM>>>(x);
    rnn_persist<<<128, 256, RNN_SMEM>>>(x, bias);
    head_kernel<<<NB, 128>>>(W1, b1, W2, b2, Wc, bc, out);
}